// round 15
// baseline (speedup 1.0000x reference)
#include <cuda_runtime.h>
#include <cuda_fp16.h>
#include <math.h>
#include <stdint.h>

#define BB 16
#define TT 2048
#define DD 1024
#define MROWS (BB * TT)       // 32768
#define LN_EPS 1e-5f

// ---- GEMM tiling ----
#define BM 128
#define BN 128
#define BK 64                  // fp16 elems per k-chunk (4 kk-steps of 16)
#define NSTAGE 3
#define NTHREADS 256
#define ROWB 144               // 128B data + 16B pad (conflict-free ldmatrix)
#define A_OFF 0
#define B_OFF (BM * ROWB)                        // 18432
#define STAGE_B  (BM * ROWB + BN * ROWB)         // 36864
#define SMEM_TOTAL (NSTAGE * STAGE_B)            // 110592 -> 2 CTAs/SM

// ---- scratch (__device__ globals; no cudaMalloc allowed) ----
__device__ __half g_xh  [(size_t)MROWS * DD];    // x fp16
__device__ __half g_big [(size_t)2 * DD * DD];   // [W_gate ; W_fused] fp16
__device__ __half g_sh  [(size_t)DD * DD];       // W_state fp16
__device__ __half g_wvt [(size_t)DD * DD];       // W_value^T fp16
__device__ __half g_uh [(size_t)MROWS * DD];     // u fp16
__device__ float g_c[(size_t)MROWS * DD];        // cand fp32; scan writes y in place

// ============================ device helpers ============================
__device__ __forceinline__ uint32_t smem_u32(const void* p) {
    uint32_t a;
    asm("{ .reg .u64 t; cvta.to.shared.u64 t, %1; cvt.u32.u64 %0, t; }" : "=r"(a) : "l"(p));
    return a;
}
__device__ __forceinline__ void cp16(uint32_t dst, const void* src) {
    asm volatile("cp.async.cg.shared.global [%0], [%1], 16;" :: "r"(dst), "l"(src));
}
__device__ __forceinline__ void cp_commit() {
    asm volatile("cp.async.commit_group;" ::: "memory");
}
template <int N>
__device__ __forceinline__ void cp_wait() {
    asm volatile("cp.async.wait_group %0;" :: "n"(N) : "memory");
}
__device__ __forceinline__ void ldsm4(uint32_t* r, uint32_t a) {
    asm volatile("ldmatrix.sync.aligned.m8n8.x4.shared.b16 {%0,%1,%2,%3}, [%4];"
                 : "=r"(r[0]), "=r"(r[1]), "=r"(r[2]), "=r"(r[3]) : "r"(a));
}
__device__ __forceinline__ void mma16816(float* c, const uint32_t* a, const uint32_t* b) {
    asm volatile(
        "mma.sync.aligned.m16n8k16.row.col.f32.f16.f16.f32 "
        "{%0,%1,%2,%3},{%4,%5,%6,%7},{%8,%9},{%0,%1,%2,%3};"
        : "+f"(c[0]), "+f"(c[1]), "+f"(c[2]), "+f"(c[3])
        : "r"(a[0]), "r"(a[1]), "r"(a[2]), "r"(a[3]), "r"(b[0]), "r"(b[1]));
}

// ============================ conversions ============================
__global__ __launch_bounds__(256) void conv_kernel(
    const float* __restrict__ src, __half* __restrict__ dst, int n)
{
    int i = (blockIdx.x * blockDim.x + threadIdx.x) * 4;
    if (i < n) {
        float4 v = *(const float4*)(src + i);
        unsigned short hb[4];
        hb[0] = __half_as_ushort(__float2half_rn(v.x));
        hb[1] = __half_as_ushort(__float2half_rn(v.y));
        hb[2] = __half_as_ushort(__float2half_rn(v.z));
        hb[3] = __half_as_ushort(__float2half_rn(v.w));
        *(uint2*)(dst + i) = make_uint2((uint32_t)hb[0] | ((uint32_t)hb[1] << 16),
                                        (uint32_t)hb[2] | ((uint32_t)hb[3] << 16));
    }
}

// fp32 -> fp16, transposed: dst[k*DD + d] = src[d*DD + k]
__global__ __launch_bounds__(256) void transpose_conv_kernel(
    const float* __restrict__ src, __half* __restrict__ dst)
{
    __shared__ __half tile[32][33];
    int k0 = blockIdx.x * 32;
    int d0 = blockIdx.y * 32;
    int tx = threadIdx.x & 31;
    int ty = threadIdx.x >> 5;
#pragma unroll
    for (int j = 0; j < 4; j++) {
        int d = d0 + ty + j * 8;
        tile[ty + j * 8][tx] = __float2half_rn(src[(size_t)d * DD + k0 + tx]);
    }
    __syncthreads();
#pragma unroll
    for (int j = 0; j < 4; j++) {
        int k = k0 + ty + j * 8;
        dst[(size_t)k * DD + d0 + tx] = tile[tx][ty + j * 8];
    }
}

// ============================ fp16 mma.sync GEMM ============================
// C[BM,BN] tile of A @ B^T.  A:[M,K] fp16 row-major, B:[N,K] fp16 row-major. K=DD.
// 256 threads: 8 warps = 4 m-slices (32) x 2 n-slices (64). 2 CTAs/SM. 3-stage ring.
// MODE 0 (combined GEMM1): bn<DD: outH = fp16(sigmoid(acc)) (u);
//                          bn>=DD: outF2 = acc (cand), col c-DD.
// MODE 2: outH2 = fp16(acc)  (W_fused = W_state @ W_value)
template <int MODE>
__global__ __launch_bounds__(NTHREADS, 2)
void gemm_mma(const __half* __restrict__ Ah, const __half* __restrict__ Bh,
              __half* __restrict__ outH, float* __restrict__ outF2,
              int ntn, int gm)
{
    extern __shared__ char smem[];
    const uint32_t sb = smem_u32(smem);
    const int tid = threadIdx.x;
    const int wid = tid >> 5, lane = tid & 31;

    int per_group = gm * ntn;
    int group = blockIdx.x / per_group;
    int rem = blockIdx.x % per_group;
    const int bm = (group * gm + (rem % gm)) * BM;
    const int bn = (rem / gm) * BN;

    const int wm = wid & 3;   // 4 m-slices of 32
    const int wn = wid >> 2;  // 2 n-slices of 64

    uint32_t offA[2], offB[4];
#pragma unroll
    for (int mf = 0; mf < 2; mf++)
        offA[mf] = (uint32_t)(wm * 32 + mf * 16 + (lane & 15)) * ROWB + (lane >> 4) * 16;
#pragma unroll
    for (int p = 0; p < 4; p++)
        offB[p] = (uint32_t)(wn * 64 + p * 16 + ((lane >> 4) & 1) * 8 + (lane & 7)) * ROWB
                  + ((lane >> 3) & 1) * 16;

    float acc[2][8][4];
#pragma unroll
    for (int a = 0; a < 2; a++)
#pragma unroll
        for (int b = 0; b < 8; b++)
#pragma unroll
            for (int e = 0; e < 4; e++) acc[a][b][e] = 0.f;

    auto load_half = [&](int kc, int half) {
        uint32_t base = sb + (uint32_t)(kc % NSTAGE) * STAGE_B;
        int k0 = kc * BK;
#pragma unroll
        for (int j = 0; j < 2; j++) {
            int ch = tid + (half * 2 + j) * NTHREADS;   // [0, 1024)
            int row = ch >> 3, kc8 = ch & 7;
            uint32_t doff = (uint32_t)row * ROWB + kc8 * 16;
            size_t ga = (size_t)(bm + row) * DD + k0 + kc8 * 8;
            cp16(base + A_OFF + doff, Ah + ga);
            size_t gb = (size_t)(bn + row) * DD + k0 + kc8 * 8;
            cp16(base + B_OFF + doff, Bh + gb);
        }
    };

    const int NKC = DD / BK;   // 16
    load_half(0, 0); load_half(0, 1); cp_commit();
    load_half(1, 0); load_half(1, 1); cp_commit();

    for (int kc = 0; kc < NKC; kc++) {
        if (kc + 1 < NKC) cp_wait<1>(); else cp_wait<0>();
        __syncthreads();

        uint32_t base = sb + (uint32_t)(kc % NSTAGE) * STAGE_B;
#pragma unroll
        for (int kk = 0; kk < 4; kk++) {
            uint32_t ah[2][4], bh[4][4];
#pragma unroll
            for (int mf = 0; mf < 2; mf++)
                ldsm4(ah[mf], base + A_OFF + offA[mf] + kk * 32);
#pragma unroll
            for (int p = 0; p < 4; p++)
                ldsm4(bh[p], base + B_OFF + offB[p] + kk * 32);
            if (kc + 2 < NKC) {
                if (kk == 0) load_half(kc + 2, 0);
                if (kk == 1) { load_half(kc + 2, 1); cp_commit(); }
            }
#pragma unroll
            for (int mf = 0; mf < 2; mf++) {
#pragma unroll
                for (int nf = 0; nf < 8; nf++) {
                    const uint32_t* b2 = &bh[nf >> 1][(nf & 1) * 2];
                    mma16816(acc[mf][nf], ah[mf], b2);
                }
            }
        }
    }

    // ---- epilogue ----
    const int r0 = bm + wm * 32 + (lane >> 2);
    const int c0 = bn + wn * 64 + (lane & 3) * 2;
    const bool gate = (MODE == 0) && (bn < DD);

#pragma unroll
    for (int mf = 0; mf < 2; mf++) {
        int r = r0 + mf * 16;
#pragma unroll
        for (int nf = 0; nf < 8; nf++) {
            int c = c0 + nf * 8;
            float* a = acc[mf][nf];
            if (MODE == 0) {
                if (gate) {
                    float s0 = 1.f / (1.f + __expf(-a[0]));
                    float s1 = 1.f / (1.f + __expf(-a[1]));
                    float s2 = 1.f / (1.f + __expf(-a[2]));
                    float s3 = 1.f / (1.f + __expf(-a[3]));
                    *(__half2*)(outH + (size_t)r * DD + c)       = __floats2half2_rn(s0, s1);
                    *(__half2*)(outH + (size_t)(r + 8) * DD + c) = __floats2half2_rn(s2, s3);
                } else {
                    int cc = c - DD;
                    *(float2*)(outF2 + (size_t)r * DD + cc)       = make_float2(a[0], a[1]);
                    *(float2*)(outF2 + (size_t)(r + 8) * DD + cc) = make_float2(a[2], a[3]);
                }
            } else {
                *(__half2*)(outH + (size_t)r * DD + c)       = __floats2half2_rn(a[0], a[1]);
                *(__half2*)(outH + (size_t)(r + 8) * DD + c) = __floats2half2_rn(a[2], a[3]);
            }
        }
    }
}

// ============================ scan (diagonal recurrence) ============================
// h_t = u*h + (1-u)*c = fma(u, h-c, c). Reads g_uh (fp16), g_c; writes y in-place into g_c.
__global__ __launch_bounds__(256) void scan_kernel()
{
    int idx = blockIdx.x * blockDim.x + threadIdx.x;   // 0 .. B*D-1
    int b = idx >> 10;
    int d = idx & (DD - 1);
    const __half* up = g_uh + (size_t)b * TT * DD + d;
    float* cp = g_c + (size_t)b * TT * DD + d;
    float h = 0.f;
    for (int t = 0; t < TT; t += 16) {
        float uu[16], cc[16];
#pragma unroll
        for (int j = 0; j < 16; j++) {
            uu[j] = __half2float(up[(size_t)(t + j) * DD]);
            cc[j] = cp[(size_t)(t + j) * DD];
        }
#pragma unroll
        for (int j = 0; j < 16; j++) {
            h = fmaf(uu[j], h - cc[j], cc[j]);
            cc[j] = h;
        }
#pragma unroll
        for (int j = 0; j < 16; j++) cp[(size_t)(t + j) * DD] = cc[j];
    }
}

// ============================ LayerNorm ============================
__global__ __launch_bounds__(256) void ln_kernel(const float* __restrict__ gamma,
                                                 const float* __restrict__ beta,
                                                 float* __restrict__ out)
{
    int row = blockIdx.x;
    int t = threadIdx.x;
    const float4* yr = (const float4*)(g_c + (size_t)row * DD);
    float4 v = yr[t];
    float s = v.x + v.y + v.z + v.w;
    float q = v.x * v.x + v.y * v.y + v.z * v.z + v.w * v.w;

#pragma unroll
    for (int o = 16; o; o >>= 1) {
        s += __shfl_xor_sync(0xFFFFFFFFu, s, o);
        q += __shfl_xor_sync(0xFFFFFFFFu, q, o);
    }
    __shared__ float sw[8], qw[8];
    __shared__ float mu_s, inv_s;
    int w = t >> 5, l = t & 31;
    if (l == 0) { sw[w] = s; qw[w] = q; }
    __syncthreads();
    if (t == 0) {
        float S = 0.f, Q = 0.f;
#pragma unroll
        for (int i = 0; i < 8; i++) { S += sw[i]; Q += qw[i]; }
        float mu = S * (1.f / DD);
        float var = Q * (1.f / DD) - mu * mu;
        mu_s = mu;
        inv_s = rsqrtf(var + LN_EPS);
    }
    __syncthreads();
    float mu = mu_s, inv = inv_s;

    const float4* g4 = (const float4*)gamma;
    const float4* b4 = (const float4*)beta;
    float4 gv = g4[t], bv = b4[t];
    float4 o;
    o.x = (v.x - mu) * inv * gv.x + bv.x;
    o.y = (v.y - mu) * inv * gv.y + bv.y;
    o.z = (v.z - mu) * inv * gv.z + bv.z;
    o.w = (v.w - mu) * inv * gv.w + bv.w;
    ((float4*)(out + (size_t)row * DD))[t] = o;
}

// ============================ host ============================
extern "C" void kernel_launch(void* const* d_in, const int* in_sizes, int n_in,
                              void* d_out, int out_size)
{
    const float* x       = (const float*)d_in[0];
    const float* W_in    = (const float*)d_in[1];
    const float* W_state = (const float*)d_in[2];
    const float* gamma   = (const float*)d_in[3];
    const float* beta    = (const float*)d_in[4];
    float* out = (float*)d_out;

    void *pxh, *pbig, *psh, *pwvt, *puh, *pc;
    cudaGetSymbolAddress(&pxh, g_xh);
    cudaGetSymbolAddress(&pbig, g_big);
    cudaGetSymbolAddress(&psh, g_sh);
    cudaGetSymbolAddress(&pwvt, g_wvt);
    cudaGetSymbolAddress(&puh, g_uh);
    cudaGetSymbolAddress(&pc,  g_c);

    cudaFuncSetAttribute((const void*)gemm_mma<0>, cudaFuncAttributeMaxDynamicSharedMemorySize, SMEM_TOTAL);
    cudaFuncSetAttribute((const void*)gemm_mma<2>, cudaFuncAttributeMaxDynamicSharedMemorySize, SMEM_TOTAL);

    // conversions
    { int n = MROWS * DD;  conv_kernel<<<(n / 4 + 255) / 256, 256>>>(x, (__half*)pxh, n); }
    { int n = DD * DD;     conv_kernel<<<(n / 4 + 255) / 256, 256>>>(W_in, (__half*)pbig, n); }
    { int n = DD * DD;     conv_kernel<<<(n / 4 + 255) / 256, 256>>>(W_state, (__half*)psh, n); }
    {
        dim3 g(DD / 32, DD / 32);
        transpose_conv_kernel<<<g, 256>>>(W_in + (size_t)DD * DD, (__half*)pwvt);
    }

    // W_fused = W_state @ W_value -> g_big[D*D : 2*D*D] (fp16)
    gemm_mma<2><<<(DD / BM) * (DD / BN), NTHREADS, SMEM_TOTAL>>>(
        (const __half*)psh, (const __half*)pwvt,
        (__half*)pbig + (size_t)DD * DD, nullptr, DD / BN, 8);

    // Combined GEMM1: x @ [W_gate ; W_fused]^T -> u (fp16 sigmoid) + cand (fp32)
    {
        int ntm = MROWS / BM, ntn = 2 * DD / BN;   // 256, 16
        gemm_mma<0><<<ntm * ntn, NTHREADS, SMEM_TOTAL>>>(
            (const __half*)pxh, (const __half*)pbig,
            (__half*)puh, (float*)pc, ntn, 16);
    }

    // scan over T (y written in-place into g_c), then LN
    scan_kernel<<<(BB * DD) / 256, 256>>>();
    ln_kernel<<<MROWS, 256>>>(gamma, beta, out);
}

// round 16
// speedup vs baseline: 1.0201x; 1.0201x over previous
#include <cuda_runtime.h>
#include <cuda_fp16.h>
#include <math.h>
#include <stdint.h>

#define BB 16
#define TT 2048
#define DD 1024
#define MROWS (BB * TT)       // 32768
#define LN_EPS 1e-5f

// ---- GEMM tiling (R14 proven shape: 2-stage, 73KB smem, 2 CTAs/SM) ----
#define BM 128
#define BN 128
#define BK 64                  // fp16 elems per k-chunk (4 kk-steps of 16)
#define NSTAGE 2
#define NTHREADS 256
#define ROWB 144               // 128B data + 16B pad (conflict-free ldmatrix)
#define A_OFF 0
#define B_OFF (BM * ROWB)                        // 18432
#define STAGE_B  (BM * ROWB + BN * ROWB)         // 36864
#define SMEM_TOTAL (NSTAGE * STAGE_B)            // 73728 -> 2 CTAs/SM

// ---- scratch (__device__ globals; no cudaMalloc allowed) ----
__device__ __half g_xh  [(size_t)MROWS * DD];    // x fp16
__device__ __half g_big [(size_t)2 * DD * DD];   // [W_gate ; W_fused] fp16
__device__ __half g_sh  [(size_t)DD * DD];       // W_state fp16
__device__ __half g_wvt [(size_t)DD * DD];       // W_value^T fp16
__device__ __half g_uh  [(size_t)MROWS * DD];    // u fp16
__device__ float g_c[(size_t)MROWS * DD];        // cand fp32; scan writes y in place

// ============================ device helpers ============================
__device__ __forceinline__ uint32_t smem_u32(const void* p) {
    uint32_t a;
    asm("{ .reg .u64 t; cvta.to.shared.u64 t, %1; cvt.u32.u64 %0, t; }" : "=r"(a) : "l"(p));
    return a;
}
__device__ __forceinline__ void cp16(uint32_t dst, const void* src) {
    asm volatile("cp.async.cg.shared.global [%0], [%1], 16;" :: "r"(dst), "l"(src));
}
__device__ __forceinline__ void cp_commit() {
    asm volatile("cp.async.commit_group;" ::: "memory");
}
template <int N>
__device__ __forceinline__ void cp_wait() {
    asm volatile("cp.async.wait_group %0;" :: "n"(N) : "memory");
}
__device__ __forceinline__ void ldsm4(uint32_t* r, uint32_t a) {
    asm volatile("ldmatrix.sync.aligned.m8n8.x4.shared.b16 {%0,%1,%2,%3}, [%4];"
                 : "=r"(r[0]), "=r"(r[1]), "=r"(r[2]), "=r"(r[3]) : "r"(a));
}
__device__ __forceinline__ void mma16816(float* c, const uint32_t* a, const uint32_t* b) {
    asm volatile(
        "mma.sync.aligned.m16n8k16.row.col.f32.f16.f16.f32 "
        "{%0,%1,%2,%3},{%4,%5,%6,%7},{%8,%9},{%0,%1,%2,%3};"
        : "+f"(c[0]), "+f"(c[1]), "+f"(c[2]), "+f"(c[3])
        : "r"(a[0]), "r"(a[1]), "r"(a[2]), "r"(a[3]), "r"(b[0]), "r"(b[1]));
}

// ============================ conversions ============================
__global__ __launch_bounds__(256) void conv_kernel(
    const float* __restrict__ src, __half* __restrict__ dst, int n)
{
    int i = (blockIdx.x * blockDim.x + threadIdx.x) * 4;
    if (i < n) {
        float4 v = *(const float4*)(src + i);
        unsigned short hb[4];
        hb[0] = __half_as_ushort(__float2half_rn(v.x));
        hb[1] = __half_as_ushort(__float2half_rn(v.y));
        hb[2] = __half_as_ushort(__float2half_rn(v.z));
        hb[3] = __half_as_ushort(__float2half_rn(v.w));
        *(uint2*)(dst + i) = make_uint2((uint32_t)hb[0] | ((uint32_t)hb[1] << 16),
                                        (uint32_t)hb[2] | ((uint32_t)hb[3] << 16));
    }
}

// fp32 -> fp16, transposed: dst[k*DD + d] = src[d*DD + k]
__global__ __launch_bounds__(256) void transpose_conv_kernel(
    const float* __restrict__ src, __half* __restrict__ dst)
{
    __shared__ __half tile[32][33];
    int k0 = blockIdx.x * 32;
    int d0 = blockIdx.y * 32;
    int tx = threadIdx.x & 31;
    int ty = threadIdx.x >> 5;
#pragma unroll
    for (int j = 0; j < 4; j++) {
        int d = d0 + ty + j * 8;
        tile[ty + j * 8][tx] = __float2half_rn(src[(size_t)d * DD + k0 + tx]);
    }
    __syncthreads();
#pragma unroll
    for (int j = 0; j < 4; j++) {
        int k = k0 + ty + j * 8;
        dst[(size_t)k * DD + d0 + tx] = tile[tx][ty + j * 8];
    }
}

// ============================ fp16 mma.sync GEMM ============================
// C[BM,BN] tile of A @ B^T.  A:[M,K] fp16 row-major, B:[N,K] fp16 row-major. K=DD.
// 256 threads: 8 warps = 4 m-slices (32) x 2 n-slices (64). 2 CTAs/SM. 2-stage ring.
// MODE 0 (combined GEMM1): bn<DD: outH = fp16(sigmoid(acc)) (u);
//                          bn>=DD: outF2 = acc (cand), col c-DD.
// MODE 2: outH = fp16(acc)  (W_fused = W_state @ W_value)
template <int MODE>
__global__ __launch_bounds__(NTHREADS, 2)
void gemm_mma(const __half* __restrict__ Ah, const __half* __restrict__ Bh,
              __half* __restrict__ outH, float* __restrict__ outF2,
              int ntn, int gm)
{
    extern __shared__ char smem[];
    const uint32_t sb = smem_u32(smem);
    const int tid = threadIdx.x;
    const int wid = tid >> 5, lane = tid & 31;

    int per_group = gm * ntn;
    int group = blockIdx.x / per_group;
    int rem = blockIdx.x % per_group;
    const int bm = (group * gm + (rem % gm)) * BM;
    const int bn = (rem / gm) * BN;

    const int wm = wid & 3;   // 4 m-slices of 32
    const int wn = wid >> 2;  // 2 n-slices of 64

    uint32_t offA[2], offB[4];
#pragma unroll
    for (int mf = 0; mf < 2; mf++)
        offA[mf] = (uint32_t)(wm * 32 + mf * 16 + (lane & 15)) * ROWB + (lane >> 4) * 16;
#pragma unroll
    for (int p = 0; p < 4; p++)
        offB[p] = (uint32_t)(wn * 64 + p * 16 + ((lane >> 4) & 1) * 8 + (lane & 7)) * ROWB
                  + ((lane >> 3) & 1) * 16;

    float acc[2][8][4];
#pragma unroll
    for (int a = 0; a < 2; a++)
#pragma unroll
        for (int b = 0; b < 8; b++)
#pragma unroll
            for (int e = 0; e < 4; e++) acc[a][b][e] = 0.f;

    auto load_half = [&](int kc, int half) {
        uint32_t base = sb + (uint32_t)(kc % NSTAGE) * STAGE_B;
        int k0 = kc * BK;
#pragma unroll
        for (int j = 0; j < 2; j++) {
            int ch = tid + (half * 2 + j) * NTHREADS;   // [0, 1024)
            int row = ch >> 3, kc8 = ch & 7;
            uint32_t doff = (uint32_t)row * ROWB + kc8 * 16;
            size_t ga = (size_t)(bm + row) * DD + k0 + kc8 * 8;
            cp16(base + A_OFF + doff, Ah + ga);
            size_t gb = (size_t)(bn + row) * DD + k0 + kc8 * 8;
            cp16(base + B_OFF + doff, Bh + gb);
        }
    };

    load_half(0, 0);
    load_half(0, 1);
    cp_commit();

    const int NKC = DD / BK;   // 16
    for (int kc = 0; kc < NKC; kc++) {
        cp_wait<0>();
        __syncthreads();

        uint32_t base = sb + (uint32_t)(kc % NSTAGE) * STAGE_B;
#pragma unroll
        for (int kk = 0; kk < 4; kk++) {
            uint32_t ah[2][4], bh[4][4];
#pragma unroll
            for (int mf = 0; mf < 2; mf++)
                ldsm4(ah[mf], base + A_OFF + offA[mf] + kk * 32);
#pragma unroll
            for (int p = 0; p < 4; p++)
                ldsm4(bh[p], base + B_OFF + offB[p] + kk * 32);
            if (kc + 1 < NKC) {
                if (kk == 0) load_half(kc + 1, 0);
                if (kk == 1) { load_half(kc + 1, 1); cp_commit(); }
            }
#pragma unroll
            for (int mf = 0; mf < 2; mf++) {
#pragma unroll
                for (int nf = 0; nf < 8; nf++) {
                    const uint32_t* b2 = &bh[nf >> 1][(nf & 1) * 2];
                    mma16816(acc[mf][nf], ah[mf], b2);
                }
            }
        }
    }

    // ---- epilogue ----
    const int r0 = bm + wm * 32 + (lane >> 2);
    const int c0 = bn + wn * 64 + (lane & 3) * 2;
    const bool gate = (MODE == 0) && (bn < DD);

#pragma unroll
    for (int mf = 0; mf < 2; mf++) {
        int r = r0 + mf * 16;
#pragma unroll
        for (int nf = 0; nf < 8; nf++) {
            int c = c0 + nf * 8;
            float* a = acc[mf][nf];
            if (MODE == 0) {
                if (gate) {
                    float s0 = 1.f / (1.f + __expf(-a[0]));
                    float s1 = 1.f / (1.f + __expf(-a[1]));
                    float s2 = 1.f / (1.f + __expf(-a[2]));
                    float s3 = 1.f / (1.f + __expf(-a[3]));
                    *(__half2*)(outH + (size_t)r * DD + c)       = __floats2half2_rn(s0, s1);
                    *(__half2*)(outH + (size_t)(r + 8) * DD + c) = __floats2half2_rn(s2, s3);
                } else {
                    int cc = c - DD;
                    *(float2*)(outF2 + (size_t)r * DD + cc)       = make_float2(a[0], a[1]);
                    *(float2*)(outF2 + (size_t)(r + 8) * DD + cc) = make_float2(a[2], a[3]);
                }
            } else {
                *(__half2*)(outH + (size_t)r * DD + c)       = __floats2half2_rn(a[0], a[1]);
                *(__half2*)(outH + (size_t)(r + 8) * DD + c) = __floats2half2_rn(a[2], a[3]);
            }
        }
    }
}

// ============================ scan (diagonal recurrence) ============================
// h_t = u*h + (1-u)*c = fma(u, h-c, c). Reads g_uh (fp16), g_c; writes y in-place into g_c.
// 64 threads/CTA -> 256 CTAs -> all 148 SMs participate.
__global__ __launch_bounds__(64) void scan_kernel()
{
    int idx = blockIdx.x * 64 + threadIdx.x;   // 0 .. B*D-1
    int b = idx >> 10;
    int d = idx & (DD - 1);
    const __half* up = g_uh + (size_t)b * TT * DD + d;
    float* cp = g_c + (size_t)b * TT * DD + d;
    float h = 0.f;
    for (int t = 0; t < TT; t += 16) {
        float uu[16], cc[16];
#pragma unroll
        for (int j = 0; j < 16; j++) {
            uu[j] = __half2float(up[(size_t)(t + j) * DD]);
            cc[j] = cp[(size_t)(t + j) * DD];
        }
#pragma unroll
        for (int j = 0; j < 16; j++) {
            h = fmaf(uu[j], h - cc[j], cc[j]);
            cc[j] = h;
        }
#pragma unroll
        for (int j = 0; j < 16; j++) cp[(size_t)(t + j) * DD] = cc[j];
    }
}

// ============================ LayerNorm ============================
__global__ __launch_bounds__(256) void ln_kernel(const float* __restrict__ gamma,
                                                 const float* __restrict__ beta,
                                                 float* __restrict__ out)
{
    int row = blockIdx.x;
    int t = threadIdx.x;
    const float4* yr = (const float4*)(g_c + (size_t)row * DD);
    float4 v = yr[t];
    float s = v.x + v.y + v.z + v.w;
    float q = v.x * v.x + v.y * v.y + v.z * v.z + v.w * v.w;

#pragma unroll
    for (int o = 16; o; o >>= 1) {
        s += __shfl_xor_sync(0xFFFFFFFFu, s, o);
        q += __shfl_xor_sync(0xFFFFFFFFu, q, o);
    }
    __shared__ float sw[8], qw[8];
    __shared__ float mu_s, inv_s;
    int w = t >> 5, l = t & 31;
    if (l == 0) { sw[w] = s; qw[w] = q; }
    __syncthreads();
    if (t == 0) {
        float S = 0.f, Q = 0.f;
#pragma unroll
        for (int i = 0; i < 8; i++) { S += sw[i]; Q += qw[i]; }
        float mu = S * (1.f / DD);
        float var = Q * (1.f / DD) - mu * mu;
        mu_s = mu;
        inv_s = rsqrtf(var + LN_EPS);
    }
    __syncthreads();
    float mu = mu_s, inv = inv_s;

    const float4* g4 = (const float4*)gamma;
    const float4* b4 = (const float4*)beta;
    float4 gv = g4[t], bv = b4[t];
    float4 o;
    o.x = (v.x - mu) * inv * gv.x + bv.x;
    o.y = (v.y - mu) * inv * gv.y + bv.y;
    o.z = (v.z - mu) * inv * gv.z + bv.z;
    o.w = (v.w - mu) * inv * gv.w + bv.w;
    ((float4*)(out + (size_t)row * DD))[t] = o;
}

// ============================ host ============================
extern "C" void kernel_launch(void* const* d_in, const int* in_sizes, int n_in,
                              void* d_out, int out_size)
{
    const float* x       = (const float*)d_in[0];
    const float* W_in    = (const float*)d_in[1];
    const float* W_state = (const float*)d_in[2];
    const float* gamma   = (const float*)d_in[3];
    const float* beta    = (const float*)d_in[4];
    float* out = (float*)d_out;

    void *pxh, *pbig, *psh, *pwvt, *puh, *pc;
    cudaGetSymbolAddress(&pxh, g_xh);
    cudaGetSymbolAddress(&pbig, g_big);
    cudaGetSymbolAddress(&psh, g_sh);
    cudaGetSymbolAddress(&pwvt, g_wvt);
    cudaGetSymbolAddress(&puh, g_uh);
    cudaGetSymbolAddress(&pc,  g_c);

    cudaFuncSetAttribute((const void*)gemm_mma<0>, cudaFuncAttributeMaxDynamicSharedMemorySize, SMEM_TOTAL);
    cudaFuncSetAttribute((const void*)gemm_mma<2>, cudaFuncAttributeMaxDynamicSharedMemorySize, SMEM_TOTAL);

    // conversions
    { int n = MROWS * DD;  conv_kernel<<<(n / 4 + 255) / 256, 256>>>(x, (__half*)pxh, n); }
    { int n = DD * DD;     conv_kernel<<<(n / 4 + 255) / 256, 256>>>(W_in, (__half*)pbig, n); }
    { int n = DD * DD;     conv_kernel<<<(n / 4 + 255) / 256, 256>>>(W_state, (__half*)psh, n); }
    {
        dim3 g(DD / 32, DD / 32);
        transpose_conv_kernel<<<g, 256>>>(W_in + (size_t)DD * DD, (__half*)pwvt);
    }

    // W_fused = W_state @ W_value -> g_big[D*D : 2*D*D] (fp16)
    gemm_mma<2><<<(DD / BM) * (DD / BN), NTHREADS, SMEM_TOTAL>>>(
        (const __half*)psh, (const __half*)pwvt,
        (__half*)pbig + (size_t)DD * DD, nullptr, DD / BN, 8);

    // Combined GEMM1: x @ [W_gate ; W_fused]^T -> u (fp16 sigmoid) + cand (fp32)
    {
        int ntm = MROWS / BM, ntn = 2 * DD / BN;   // 256, 16
        gemm_mma<0><<<ntm * ntn, NTHREADS, SMEM_TOTAL>>>(
            (const __half*)pxh, (const __half*)pbig,
            (__half*)puh, (float*)pc, ntn, 16);
    }

    // scan over T (y written in-place into g_c), then LN
    scan_kernel<<<(BB * DD) / 64, 64>>>();
    ln_kernel<<<MROWS, 256>>>(gamma, beta, out);
}

// round 17
// speedup vs baseline: 1.0390x; 1.0185x over previous
#include <cuda_runtime.h>
#include <cuda_fp16.h>
#include <math.h>
#include <stdint.h>

#define BB 16
#define TT 2048
#define DD 1024
#define MROWS (BB * TT)       // 32768
#define LN_EPS 1e-5f

// ---- GEMM tiling (R14 proven shape: 2-stage, 73KB smem, 2 CTAs/SM) ----
#define BM 128
#define BN 128
#define BK 64                  // fp16 elems per k-chunk (4 kk-steps of 16)
#define NSTAGE 2
#define NTHREADS 256
#define ROWB 144               // 128B data + 16B pad (conflict-free ldmatrix)
#define A_OFF 0
#define B_OFF (BM * ROWB)                        // 18432
#define STAGE_B  (BM * ROWB + BN * ROWB)         // 36864
#define SMEM_TOTAL (NSTAGE * STAGE_B)            // 73728 -> 2 CTAs/SM

// ---- scratch (__device__ globals; no cudaMalloc allowed) ----
__device__ __half g_xh  [(size_t)MROWS * DD];    // x fp16
__device__ __half g_big [(size_t)2 * DD * DD];   // [W_gate ; W_fused] fp16
__device__ __half g_sh  [(size_t)DD * DD];       // W_state fp16
__device__ __half g_wvt [(size_t)DD * DD];       // W_value^T fp16
__device__ float g_u[(size_t)MROWS * DD];        // u fp32
__device__ float g_c[(size_t)MROWS * DD];        // cand fp32; scan writes y in place

// ============================ device helpers ============================
__device__ __forceinline__ uint32_t smem_u32(const void* p) {
    uint32_t a;
    asm("{ .reg .u64 t; cvta.to.shared.u64 t, %1; cvt.u32.u64 %0, t; }" : "=r"(a) : "l"(p));
    return a;
}
__device__ __forceinline__ void cp16(uint32_t dst, const void* src) {
    asm volatile("cp.async.cg.shared.global [%0], [%1], 16;" :: "r"(dst), "l"(src));
}
__device__ __forceinline__ void cp_commit() {
    asm volatile("cp.async.commit_group;" ::: "memory");
}
template <int N>
__device__ __forceinline__ void cp_wait() {
    asm volatile("cp.async.wait_group %0;" :: "n"(N) : "memory");
}
__device__ __forceinline__ void ldsm4(uint32_t* r, uint32_t a) {
    asm volatile("ldmatrix.sync.aligned.m8n8.x4.shared.b16 {%0,%1,%2,%3}, [%4];"
                 : "=r"(r[0]), "=r"(r[1]), "=r"(r[2]), "=r"(r[3]) : "r"(a));
}
__device__ __forceinline__ void mma16816(float* c, const uint32_t* a, const uint32_t* b) {
    asm volatile(
        "mma.sync.aligned.m16n8k16.row.col.f32.f16.f16.f32 "
        "{%0,%1,%2,%3},{%4,%5,%6,%7},{%8,%9},{%0,%1,%2,%3};"
        : "+f"(c[0]), "+f"(c[1]), "+f"(c[2]), "+f"(c[3])
        : "r"(a[0]), "r"(a[1]), "r"(a[2]), "r"(a[3]), "r"(b[0]), "r"(b[1]));
}

__device__ __forceinline__ void conv4(const float* __restrict__ src, __half* __restrict__ dst, int i) {
    float4 v = *(const float4*)(src + i);
    unsigned short hb[4];
    hb[0] = __half_as_ushort(__float2half_rn(v.x));
    hb[1] = __half_as_ushort(__float2half_rn(v.y));
    hb[2] = __half_as_ushort(__float2half_rn(v.z));
    hb[3] = __half_as_ushort(__float2half_rn(v.w));
    *(uint2*)(dst + i) = make_uint2((uint32_t)hb[0] | ((uint32_t)hb[1] << 16),
                                    (uint32_t)hb[2] | ((uint32_t)hb[3] << 16));
}

// ============================ merged prep kernel ============================
// blocks [0, 32768):          x fp32 -> fp16                (256 thr x 4 elems)
// blocks [32768, 33792):      W_gate fp32 -> fp16
// blocks [33792, 34816):      W_state fp32 -> fp16
// blocks [34816, 35840):      W_value fp32 -> fp16 transposed (32x32 tiles)
#define XB   (MROWS * DD / 1024)     // 32768
#define WB   (DD * DD / 1024)        // 1024
__global__ __launch_bounds__(256) void prep_kernel(
    const float* __restrict__ x, const float* __restrict__ W_in,
    const float* __restrict__ W_state,
    __half* __restrict__ xh, __half* __restrict__ big,
    __half* __restrict__ sh, __half* __restrict__ wvt)
{
    __shared__ __half tile[32][33];
    int b = blockIdx.x;
    int tid = threadIdx.x;
    if (b < XB) {
        conv4(x, xh, (b * 256 + tid) * 4);
    } else if (b < XB + WB) {
        conv4(W_in, big, ((b - XB) * 256 + tid) * 4);
    } else if (b < XB + 2 * WB) {
        conv4(W_state, sh, ((b - XB - WB) * 256 + tid) * 4);
    } else {
        int id = b - (XB + 2 * WB);          // 0..1023
        const float* src = W_in + (size_t)DD * DD;   // W_value
        int k0 = (id & 31) * 32;
        int d0 = (id >> 5) * 32;
        int tx = tid & 31;
        int ty = tid >> 5;
#pragma unroll
        for (int j = 0; j < 4; j++) {
            int d = d0 + ty + j * 8;
            tile[ty + j * 8][tx] = __float2half_rn(src[(size_t)d * DD + k0 + tx]);
        }
        __syncthreads();
#pragma unroll
        for (int j = 0; j < 4; j++) {
            int k = k0 + ty + j * 8;
            wvt[(size_t)k * DD + d0 + tx] = tile[tx][ty + j * 8];
        }
    }
}

// ============================ fp16 mma.sync GEMM ============================
// C[BM,BN] tile of A @ B^T.  A:[M,K] fp16 row-major, B:[N,K] fp16 row-major. K=DD.
// 256 threads: 8 warps = 4 m-slices (32) x 2 n-slices (64). 2 CTAs/SM. 2-stage ring.
// MODE 0 (combined GEMM1): bn<DD: outF = sigmoid(acc) fp32 (u);
//                          bn>=DD: outF2 = acc (cand), col c-DD.
// MODE 2: outH = fp16(acc)  (W_fused = W_state @ W_value)
template <int MODE>
__global__ __launch_bounds__(NTHREADS, 2)
void gemm_mma(const __half* __restrict__ Ah, const __half* __restrict__ Bh,
              float* __restrict__ outF, float* __restrict__ outF2,
              __half* __restrict__ outH, int ntn, int gm)
{
    extern __shared__ char smem[];
    const uint32_t sb = smem_u32(smem);
    const int tid = threadIdx.x;
    const int wid = tid >> 5, lane = tid & 31;

    int per_group = gm * ntn;
    int group = blockIdx.x / per_group;
    int rem = blockIdx.x % per_group;
    const int bm = (group * gm + (rem % gm)) * BM;
    const int bn = (rem / gm) * BN;

    const int wm = wid & 3;   // 4 m-slices of 32
    const int wn = wid >> 2;  // 2 n-slices of 64

    uint32_t offA[2], offB[4];
#pragma unroll
    for (int mf = 0; mf < 2; mf++)
        offA[mf] = (uint32_t)(wm * 32 + mf * 16 + (lane & 15)) * ROWB + (lane >> 4) * 16;
#pragma unroll
    for (int p = 0; p < 4; p++)
        offB[p] = (uint32_t)(wn * 64 + p * 16 + ((lane >> 4) & 1) * 8 + (lane & 7)) * ROWB
                  + ((lane >> 3) & 1) * 16;

    float acc[2][8][4];
#pragma unroll
    for (int a = 0; a < 2; a++)
#pragma unroll
        for (int b = 0; b < 8; b++)
#pragma unroll
            for (int e = 0; e < 4; e++) acc[a][b][e] = 0.f;

    auto load_half = [&](int kc, int half) {
        uint32_t base = sb + (uint32_t)(kc % NSTAGE) * STAGE_B;
        int k0 = kc * BK;
#pragma unroll
        for (int j = 0; j < 2; j++) {
            int ch = tid + (half * 2 + j) * NTHREADS;   // [0, 1024)
            int row = ch >> 3, kc8 = ch & 7;
            uint32_t doff = (uint32_t)row * ROWB + kc8 * 16;
            size_t ga = (size_t)(bm + row) * DD + k0 + kc8 * 8;
            cp16(base + A_OFF + doff, Ah + ga);
            size_t gb = (size_t)(bn + row) * DD + k0 + kc8 * 8;
            cp16(base + B_OFF + doff, Bh + gb);
        }
    };

    load_half(0, 0);
    load_half(0, 1);
    cp_commit();

    const int NKC = DD / BK;   // 16
    for (int kc = 0; kc < NKC; kc++) {
        cp_wait<0>();
        __syncthreads();

        uint32_t base = sb + (uint32_t)(kc % NSTAGE) * STAGE_B;
#pragma unroll
        for (int kk = 0; kk < 4; kk++) {
            uint32_t ah[2][4], bh[4][4];
#pragma unroll
            for (int mf = 0; mf < 2; mf++)
                ldsm4(ah[mf], base + A_OFF + offA[mf] + kk * 32);
#pragma unroll
            for (int p = 0; p < 4; p++)
                ldsm4(bh[p], base + B_OFF + offB[p] + kk * 32);
            if (kc + 1 < NKC) {
                if (kk == 0) load_half(kc + 1, 0);
                if (kk == 1) { load_half(kc + 1, 1); cp_commit(); }
            }
#pragma unroll
            for (int mf = 0; mf < 2; mf++) {
#pragma unroll
                for (int nf = 0; nf < 8; nf++) {
                    const uint32_t* b2 = &bh[nf >> 1][(nf & 1) * 2];
                    mma16816(acc[mf][nf], ah[mf], b2);
                }
            }
        }
    }

    // ---- epilogue ----
    const int r0 = bm + wm * 32 + (lane >> 2);
    const int c0 = bn + wn * 64 + (lane & 3) * 2;
    const bool gate = (MODE == 0) && (bn < DD);

#pragma unroll
    for (int mf = 0; mf < 2; mf++) {
        int r = r0 + mf * 16;
#pragma unroll
        for (int nf = 0; nf < 8; nf++) {
            int c = c0 + nf * 8;
            float* a = acc[mf][nf];
            if (MODE == 0) {
                if (gate) {
                    float2 s0, s1;
                    s0.x = 1.f / (1.f + __expf(-a[0]));
                    s0.y = 1.f / (1.f + __expf(-a[1]));
                    s1.x = 1.f / (1.f + __expf(-a[2]));
                    s1.y = 1.f / (1.f + __expf(-a[3]));
                    *(float2*)(outF + (size_t)r * DD + c)       = s0;
                    *(float2*)(outF + (size_t)(r + 8) * DD + c) = s1;
                } else {
                    int cc = c - DD;
                    *(float2*)(outF2 + (size_t)r * DD + cc)       = make_float2(a[0], a[1]);
                    *(float2*)(outF2 + (size_t)(r + 8) * DD + cc) = make_float2(a[2], a[3]);
                }
            } else {
                *(__half2*)(outH + (size_t)r * DD + c)       = __floats2half2_rn(a[0], a[1]);
                *(__half2*)(outH + (size_t)(r + 8) * DD + c) = __floats2half2_rn(a[2], a[3]);
            }
        }
    }
}

// ============================ scan (diagonal recurrence) ============================
// h_t = u*h + (1-u)*c = fma(u, h-c, c). Reads g_u, g_c; writes y in-place into g_c.
// 128 threads x 128 CTAs -> ~full-chip coverage.
__global__ __launch_bounds__(128) void scan_kernel()
{
    int idx = blockIdx.x * 128 + threadIdx.x;   // 0 .. B*D-1
    int b = idx >> 10;
    int d = idx & (DD - 1);
    float* up = g_u + (size_t)b * TT * DD + d;
    float* cp = g_c + (size_t)b * TT * DD + d;
    float h = 0.f;
    for (int t = 0; t < TT; t += 16) {
        float uu[16], cc[16];
#pragma unroll
        for (int j = 0; j < 16; j++) {
            uu[j] = up[(size_t)(t + j) * DD];
            cc[j] = cp[(size_t)(t + j) * DD];
        }
#pragma unroll
        for (int j = 0; j < 16; j++) {
            h = fmaf(uu[j], h - cc[j], cc[j]);
            cc[j] = h;
        }
#pragma unroll
        for (int j = 0; j < 16; j++) cp[(size_t)(t + j) * DD] = cc[j];
    }
}

// ============================ LayerNorm ============================
__global__ __launch_bounds__(256) void ln_kernel(const float* __restrict__ gamma,
                                                 const float* __restrict__ beta,
                                                 float* __restrict__ out)
{
    int row = blockIdx.x;
    int t = threadIdx.x;
    const float4* yr = (const float4*)(g_c + (size_t)row * DD);
    float4 v = yr[t];
    float s = v.x + v.y + v.z + v.w;
    float q = v.x * v.x + v.y * v.y + v.z * v.z + v.w * v.w;

#pragma unroll
    for (int o = 16; o; o >>= 1) {
        s += __shfl_xor_sync(0xFFFFFFFFu, s, o);
        q += __shfl_xor_sync(0xFFFFFFFFu, q, o);
    }
    __shared__ float sw[8], qw[8];
    __shared__ float mu_s, inv_s;
    int w = t >> 5, l = t & 31;
    if (l == 0) { sw[w] = s; qw[w] = q; }
    __syncthreads();
    if (t == 0) {
        float S = 0.f, Q = 0.f;
#pragma unroll
        for (int i = 0; i < 8; i++) { S += sw[i]; Q += qw[i]; }
        float mu = S * (1.f / DD);
        float var = Q * (1.f / DD) - mu * mu;
        mu_s = mu;
        inv_s = rsqrtf(var + LN_EPS);
    }
    __syncthreads();
    float mu = mu_s, inv = inv_s;

    const float4* g4 = (const float4*)gamma;
    const float4* b4 = (const float4*)beta;
    float4 gv = g4[t], bv = b4[t];
    float4 o;
    o.x = (v.x - mu) * inv * gv.x + bv.x;
    o.y = (v.y - mu) * inv * gv.y + bv.y;
    o.z = (v.z - mu) * inv * gv.z + bv.z;
    o.w = (v.w - mu) * inv * gv.w + bv.w;
    ((float4*)(out + (size_t)row * DD))[t] = o;
}

// ============================ host ============================
extern "C" void kernel_launch(void* const* d_in, const int* in_sizes, int n_in,
                              void* d_out, int out_size)
{
    const float* x       = (const float*)d_in[0];
    const float* W_in    = (const float*)d_in[1];
    const float* W_state = (const float*)d_in[2];
    const float* gamma   = (const float*)d_in[3];
    const float* beta    = (const float*)d_in[4];
    float* out = (float*)d_out;

    void *pxh, *pbig, *psh, *pwvt, *pu, *pc;
    cudaGetSymbolAddress(&pxh, g_xh);
    cudaGetSymbolAddress(&pbig, g_big);
    cudaGetSymbolAddress(&psh, g_sh);
    cudaGetSymbolAddress(&pwvt, g_wvt);
    cudaGetSymbolAddress(&pu,  g_u);
    cudaGetSymbolAddress(&pc,  g_c);

    cudaFuncSetAttribute((const void*)gemm_mma<0>, cudaFuncAttributeMaxDynamicSharedMemorySize, SMEM_TOTAL);
    cudaFuncSetAttribute((const void*)gemm_mma<2>, cudaFuncAttributeMaxDynamicSharedMemorySize, SMEM_TOTAL);

    // single merged prep launch: x conv + W_gate conv + W_state conv + W_value^T
    prep_kernel<<<XB + 3 * WB, 256>>>(x, W_in, W_state,
                                      (__half*)pxh, (__half*)pbig,
                                      (__half*)psh, (__half*)pwvt);

    // W_fused = W_state @ W_value -> g_big[D*D : 2*D*D] (fp16)
    gemm_mma<2><<<(DD / BM) * (DD / BN), NTHREADS, SMEM_TOTAL>>>(
        (const __half*)psh, (const __half*)pwvt,
        nullptr, nullptr, (__half*)pbig + (size_t)DD * DD, DD / BN, 8);

    // Combined GEMM1: x @ [W_gate ; W_fused]^T -> u (sigmoid fp32) + cand (fp32)
    {
        int ntm = MROWS / BM, ntn = 2 * DD / BN;   // 256, 16
        gemm_mma<0><<<ntm * ntn, NTHREADS, SMEM_TOTAL>>>(
            (const __half*)pxh, (const __half*)pbig,
            (float*)pu, (float*)pc, nullptr, ntn, 16);
    }

    // scan over T (y written in-place into g_c), then LN
    scan_kernel<<<(BB * DD) / 128, 128>>>();
    ln_kernel<<<MROWS, 256>>>(gamma, beta, out);
}